// round 13
// baseline (speedup 1.0000x reference)
#include <cuda_runtime.h>

#define N_NODES 20000
#define N_EDGES 50000
#define H 64
#define HH 4096
#define NREG 65
#define GE 8
#define WARPS 4
#define BLK_SLOTS (WARPS * GE)            // 32 edges per k_msg block
#define EPAD (N_EDGES + NREG * GE)
#define NPB 32
#define RBLOCKS (N_NODES / NPB)           // 625 k_root blocks

// ---------------- scratch (static zero-init is load-bearing for run #1) ----
// d_Qbuf per region r: PAIR-PERMUTED: Q0 at [r*2HH + (i>>1)*128 + 2*o + (i&1)],
// Q1 at +HH  => {Q[2c][o], Q[2c+1][o]} is one aligned float2.
__device__ __align__(16) float d_Qbuf[NREG * 2 * HH];
__device__ int   d_regid[N_EDGES];
__device__ int   d_hist[NREG];            // zeroed by k_fin each run
__device__ int   d_cursor[NREG];          // zeroed by k_fin each run
__device__ int   d_sorted[EPAD];          // 0 = empty; stores eid+1
__device__ __align__(16) float d_agg[N_NODES * H];   // zeroed by k_fin
__device__ float d_sums[2 * H];           // zeroed in k_scatter_and_zero
__device__ unsigned d_ctr;                // last-block counter (self-resetting)

__device__ __forceinline__ float bp_of(const float* w1, const float* b1, int k) {
    float w = w1[k];
    return (w == 0.0f) ? 1e30f : (-b1[k] / w);
}

// ---------------- 0) region id + histogram + (last block) cursor offsets ---
__global__ void __launch_bounds__(256) k_region(const float* ea,
                                                const float* w1,
                                                const float* b1) {
    __shared__ float tbs[H];
    __shared__ float Bs[H];
    __shared__ int   bh[NREG];
    __shared__ int   isLast;
    int t = threadIdx.x;
    if (t < H) tbs[t] = bp_of(w1, b1, t);
    if (t < NREG) bh[t] = 0;
    __syncthreads();
    if (t < H) {
        float my = tbs[t];
        int rank = 0;
        for (int j = 0; j < H; j++) {
            float tj = tbs[j];
            rank += (tj < my) || (tj == my && j < t);
        }
        Bs[rank] = my;
    }
    __syncthreads();
    int e = blockIdx.x * blockDim.x + t;
    if (e < N_EDGES) {
        float a = ea[e];
        int r = 0;
        #pragma unroll 8
        for (int k = 0; k < H; k++) r += (Bs[k] <= a) ? 1 : 0;
        d_regid[e] = r;
        atomicAdd(&bh[r], 1);
    }
    __syncthreads();
    if (t < NREG && bh[t] > 0) atomicAdd(&d_hist[t], bh[t]);
    __threadfence();
    if (t == 0) {
        unsigned prev = atomicAdd(&d_ctr, 1u);
        isLast = (prev == gridDim.x - 1) ? 1 : 0;
    }
    __syncthreads();
    if (isLast && t == 0) {
        int s = 0;
        for (int r = 0; r < NREG; r++) {
            d_cursor[r] = s;
            s += (atomicAdd(&d_hist[r], 0) + (GE - 1)) & ~(GE - 1);
        }
        d_ctr = 0;
    }
}

// ---------------- 1) scatter (+ zero d_sums for this run) ----------------
__global__ void k_scatter_and_zero() {
    int e = blockIdx.x * blockDim.x + threadIdx.x;
    if (e < 2 * H) d_sums[e] = 0.0f;
    if (e < N_EDGES) {
        int r = d_regid[e];
        int pos = atomicAdd(&d_cursor[r], 1);
        d_sorted[pos] = e + 1;
    }
}

// ---------------- 2) Q0/Q1: 8 checkpoint chunks x rank-1 updates -----------
// grid = 256: (blockIdx & 31) = m-group, (blockIdx >> 5) = chunk of 9 ranks
__global__ void __launch_bounds__(128) k_q(const float* w1, const float* b1,
                                           const float* b2, const float* w2) {
    __shared__ float w2sh[128][H + 1];
    __shared__ float tbs[H];
    __shared__ int   rankOf[H], idxOf[H];
    __shared__ float mb[H], mw[H], dB[H], dW[H];
    __shared__ int   cix[H];

    int t = threadIdx.x;
    int mg = blockIdx.x & 31, chunk = blockIdx.x >> 5;
    int r0 = chunk * 9;
    int rend = (r0 + 9 < NREG) ? r0 + 9 : NREG;
    int mbase = mg * 128;

    for (int i2 = t; i2 < 128 * H; i2 += 128) {
        int ml = i2 >> 6, k = i2 & 63;
        w2sh[ml][k] = w2[(mbase + ml) * H + k];
    }
    if (t < H) tbs[t] = bp_of(w1, b1, t);
    __syncthreads();
    if (t < H) {
        float my = tbs[t];
        int rank = 0;
        for (int j = 0; j < H; j++) {
            float tj = tbs[j];
            rank += (tj < my) || (tj == my && j < t);
        }
        rankOf[t] = rank;
        idxOf[rank] = t;
    }
    __syncthreads();
    if (t < H) {
        int k = t;
        float w = w1[k], b = b1[k];
        int rk = rankOf[k];
        bool act = (w > 0.0f) ? (rk < r0) : ((w < 0.0f) ? (rk >= r0) : (b > 0.0f));
        mb[k] = act ? b : 0.0f;
        mw[k] = act ? w : 0.0f;
        int kr = idxOf[t];
        float wr = w1[kr], br = b1[kr];
        float sgn = (wr > 0.0f) ? 1.0f : -1.0f;
        dB[t] = sgn * br;
        dW[t] = sgn * wr;
        cix[t] = kr;
    }
    __syncthreads();

    int m = mbase + t;
    int i = m >> 6, o = m & 63;
    int p = (i >> 1) * 128 + 2 * o + (i & 1);   // pair-permuted index
    const float* row = w2sh[t];
    float q0 = b2[m];
    float q1 = 0.0f;
    #pragma unroll 8
    for (int k = 0; k < H; k++) {
        float v = row[k];
        q0 = fmaf(mb[k], v, q0);
        q1 = fmaf(mw[k], v, q1);
    }
    for (int r = r0; r < rend; r++) {
        d_Qbuf[r * (2 * HH) + p]      = q0;
        d_Qbuf[r * (2 * HH) + HH + p] = q1;
        if (r < H) {
            float v = row[cix[r]];
            q0 = fmaf(dB[r], v, q0);
            q1 = fmaf(dW[r], v, q1);
        }
    }
}

// ---------------- 3) message + scatter-add (hot; warp-autonomous) ----------
__global__ void __launch_bounds__(128, 8) k_msg(const float* x, const float* ea,
                                                const int* ei) {
    __shared__ float2 xs[WARPS][GE][32];    // {x[2c], x[2c+1]} per edge
    __shared__ float  sa[WARPS][GE];
    __shared__ int    ssrc[WARPS][GE];
    __shared__ int    sdst[WARPS][GE];
    __shared__ int    sreg[WARPS][GE];

    int w = threadIdx.x >> 5;
    int lane = threadIdx.x & 31;
    int sbase = blockIdx.x * BLK_SLOTS + w * GE;

    if (lane < GE) {
        int slot = sbase + lane;
        int eid1 = (slot < EPAD) ? d_sorted[slot] : 0;
        int src = -1, dst = 0, r = -1;
        float a = 0.0f;
        if (eid1 > 0) {
            int eid = eid1 - 1;
            a = ea[eid];
            src = ei[eid];
            dst = ei[N_EDGES + eid];
            r = d_regid[eid];
            if (src < 0 || src >= N_NODES || dst < 0 || dst >= N_NODES) {
                src = -1; dst = 0;
            }
        }
        sa[w][lane] = a; ssrc[w][lane] = src;
        sdst[w][lane] = dst; sreg[w][lane] = r;
    }
    __syncwarp();
    int rr = -1;
    #pragma unroll
    for (int j = 0; j < GE; j++) { int rg = sreg[w][j]; rr = (rg > rr) ? rg : rr; }
    if (rr < 0) return;

    #pragma unroll
    for (int j = 0; j < GE; j++) {
        int s = ssrc[w][j];
        float2 v = make_float2(0.0f, 0.0f);
        if (s >= 0) v = *reinterpret_cast<const float2*>(x + s * H + 2 * lane);
        xs[w][j][lane] = v;
    }
    __syncwarp();

    const float* Qp = d_Qbuf + rr * (2 * HH);
    float a0a[GE], a1a[GE], a0b[GE], a1b[GE];
    #pragma unroll
    for (int j = 0; j < GE; j++) { a0a[j] = 0.f; a1a[j] = 0.f; a0b[j] = 0.f; a1b[j] = 0.f; }

    #pragma unroll 4
    for (int c = 0; c < 32; c++) {
        const float* base = Qp + c * 128 + 2 * lane;
        float2 q0a = *reinterpret_cast<const float2*>(base);
        float2 q0b = *reinterpret_cast<const float2*>(base + 64);
        float2 q1a = *reinterpret_cast<const float2*>(base + HH);
        float2 q1b = *reinterpret_cast<const float2*>(base + HH + 64);
        #pragma unroll
        for (int j = 0; j < GE; j++) {
            float2 xv = xs[w][j][c];
            a0a[j] = fmaf(xv.x, q0a.x, a0a[j]); a0a[j] = fmaf(xv.y, q0a.y, a0a[j]);
            a0b[j] = fmaf(xv.x, q0b.x, a0b[j]); a0b[j] = fmaf(xv.y, q0b.y, a0b[j]);
            a1a[j] = fmaf(xv.x, q1a.x, a1a[j]); a1a[j] = fmaf(xv.y, q1a.y, a1a[j]);
            a1b[j] = fmaf(xv.x, q1b.x, a1b[j]); a1b[j] = fmaf(xv.y, q1b.y, a1b[j]);
        }
    }
    #pragma unroll
    for (int j = 0; j < GE; j++) {
        bool live = (ssrc[w][j] >= 0);
        float aa = sa[w][j];
        float va = live ? fmaf(aa, a1a[j], a0a[j]) : 0.0f;
        float vb = live ? fmaf(aa, a1b[j], a0b[j]) : 0.0f;
        float vah = __shfl_down_sync(0xFFFFFFFF, va, 1);
        float vbh = __shfl_down_sync(0xFFFFFFFF, vb, 1);
        if (live && (lane & 1) == 0) {
            float* p = d_agg + sdst[w][j] * H + lane;
            asm volatile("red.global.add.v2.f32 [%0], {%1, %2};"
                         :: "l"(p), "f"(va), "f"(vah) : "memory");
            asm volatile("red.global.add.v2.f32 [%0], {%1, %2};"
                         :: "l"(p + 32), "f"(vb), "f"(vbh) : "memory");
        }
    }
}

// ---------------- 4) root GEMM + bias + agg; fewer barriers ----------------
__global__ void __launch_bounds__(256) k_root(const float* x, const float* rw,
                                              const float* cb, float* out) {
    __shared__ float rws[HH];        // transposed root_w: rws[i*64+o]
    __shared__ float xsn[NPB][H];    // all 32 nodes staged once
    __shared__ float red[256];
    int t = threadIdx.x;
    int n0 = blockIdx.x * NPB;
    for (int idx = t; idx < HH; idx += 256) {
        int oo = idx >> 6, ii = idx & 63;
        rws[ii * H + oo] = rw[idx];
    }
    for (int idx = t; idx < NPB * H; idx += 256) {
        int nl = idx >> 6, ii = idx & 63;
        xsn[nl][ii] = x[(n0 + nl) * H + ii];
    }
    __syncthreads();
    int o = t & 63, q = t >> 6;      // q = 0..3, each handles 8 nodes
    float cbo = cb[o];
    float psum = 0.0f, psq = 0.0f;
    #pragma unroll
    for (int c = 0; c < NPB / 4; c++) {
        int nl = q * (NPB / 4) + c;
        float acc = 0.0f;
        #pragma unroll 8
        for (int i = 0; i < H; i++) acc = fmaf(xsn[nl][i], rws[i * H + o], acc);
        float val = acc + d_agg[(n0 + nl) * H + o] + cbo;
        out[(n0 + nl) * H + o] = val;
        psum += val;
        psq = fmaf(val, val, psq);
    }
    red[t] = psum; __syncthreads();
    if (q < 2) red[t] += red[t + 128];
    __syncthreads();
    if (q == 0) atomicAdd(&d_sums[o], red[t] + red[t + 64]);
    __syncthreads();
    red[t] = psq; __syncthreads();
    if (q < 2) red[t] += red[t + 128];
    __syncthreads();
    if (q == 0) atomicAdd(&d_sums[H + o], red[t] + red[t + 64]);
}

// ---------------- 5) BN + relu + residual, then reset scratch for replay ---
__global__ void k_fin(const float* x, const float* gamma,
                      const float* beta, float* out) {
    int idx = blockIdx.x * blockDim.x + threadIdx.x;
    if (idx < N_NODES * H) {
        int o = idx & 63;
        const float invN = 1.0f / (float)N_NODES;
        float mean = d_sums[o] * invN;
        float var  = d_sums[H + o] * invN - mean * mean;
        float istd = rsqrtf(var + 1e-5f);
        float v = out[idx];
        float bn = fmaf((v - mean) * istd, gamma[o], beta[o]);
        out[idx] = x[idx] + fmaxf(bn, 0.0f);
        d_agg[idx] = 0.0f;
        if (idx < EPAD) d_sorted[idx] = 0;
        if (idx < NREG) { d_hist[idx] = 0; d_cursor[idx] = 0; }
    }
}

extern "C" void kernel_launch(void* const* d_in, const int* in_sizes, int n_in,
                              void* d_out, int out_size) {
    const float* x     = (const float*)d_in[0];
    const float* ea    = (const float*)d_in[1];
    const int*   ei    = (const int*)d_in[2];
    const float* w1    = (const float*)d_in[3];
    const float* b1    = (const float*)d_in[4];
    const float* w2    = (const float*)d_in[5];
    const float* b2    = (const float*)d_in[6];
    const float* rw    = (const float*)d_in[7];
    const float* cb    = (const float*)d_in[8];
    const float* gamma = (const float*)d_in[9];
    const float* beta  = (const float*)d_in[10];
    float* out = (float*)d_out;

    k_region<<<(N_EDGES + 255) / 256, 256>>>(ea, w1, b1);
    k_scatter_and_zero<<<(N_EDGES + 255) / 256, 256>>>();
    k_q<<<256, 128>>>(w1, b1, b2, w2);
    k_msg<<<(EPAD + BLK_SLOTS - 1) / BLK_SLOTS, 128>>>(x, ea, ei);  // profiled slot
    k_root<<<RBLOCKS, 256>>>(x, rw, cb, out);
    k_fin<<<(N_NODES * H + 255) / 256, 256>>>(x, gamma, beta, out);
}

// round 15
// speedup vs baseline: 1.2661x; 1.2661x over previous
#include <cuda_runtime.h>

#define N_NODES 20000
#define N_EDGES 50000
#define H 64
#define HH 4096
#define NREG 65
#define GE 8
#define WARPS 4
#define BLK_SLOTS (WARPS * GE)            // 32 edges per k_msg block
#define EPAD (N_EDGES + NREG * GE)
#define NPB 32
#define RBLOCKS (N_NODES / NPB)           // 625 k_root blocks

// ---------------- scratch (static zero-init is load-bearing for run #1) ----
// d_Qbuf per region r: PAIR-PERMUTED: Q0 at [r*2HH + (i>>1)*128 + 2*o + (i&1)],
// Q1 at +HH  => {Q[2c][o], Q[2c+1][o]} is one aligned float2.
__device__ __align__(16) float d_Qbuf[NREG * 2 * HH];
__device__ int   d_regid[N_EDGES];
__device__ int   d_hist[NREG];            // zeroed by k_fin each run
__device__ int   d_cursor[NREG];          // zeroed by k_fin each run
__device__ int   d_sorted[EPAD];          // 0 = empty; stores eid+1
__device__ __align__(16) float d_agg[N_NODES * H];   // zeroed by k_fin
__device__ float d_sums[2 * H];           // zeroed in k_scatter_and_zero
__device__ unsigned d_ctr;                // last-block counter (self-resetting)

__device__ __forceinline__ float bp_of(const float* w1, const float* b1, int k) {
    float w = w1[k];
    return (w == 0.0f) ? 1e30f : (-b1[k] / w);
}

// ---------------- 0) region id + histogram + (last block) cursor offsets ---
__global__ void __launch_bounds__(256) k_region(const float* ea,
                                                const float* w1,
                                                const float* b1) {
    __shared__ float tbs[H];
    __shared__ float Bs[H];
    __shared__ int   bh[NREG];
    __shared__ int   isLast;
    int t = threadIdx.x;
    if (t < H) tbs[t] = bp_of(w1, b1, t);
    if (t < NREG) bh[t] = 0;
    __syncthreads();
    if (t < H) {
        float my = tbs[t];
        int rank = 0;
        for (int j = 0; j < H; j++) {
            float tj = tbs[j];
            rank += (tj < my) || (tj == my && j < t);
        }
        Bs[rank] = my;
    }
    __syncthreads();
    int e = blockIdx.x * blockDim.x + t;
    if (e < N_EDGES) {
        float a = ea[e];
        int r = 0;
        #pragma unroll 8
        for (int k = 0; k < H; k++) r += (Bs[k] <= a) ? 1 : 0;
        d_regid[e] = r;
        atomicAdd(&bh[r], 1);
    }
    __syncthreads();
    if (t < NREG && bh[t] > 0) atomicAdd(&d_hist[t], bh[t]);
    __threadfence();
    if (t == 0) {
        unsigned prev = atomicAdd(&d_ctr, 1u);
        isLast = (prev == gridDim.x - 1) ? 1 : 0;
    }
    __syncthreads();
    if (isLast && t == 0) {
        int s = 0;
        for (int r = 0; r < NREG; r++) {
            d_cursor[r] = s;
            s += (atomicAdd(&d_hist[r], 0) + (GE - 1)) & ~(GE - 1);
        }
        d_ctr = 0;
    }
}

// ---------------- 1) scatter (+ zero d_sums for this run) ----------------
__global__ void k_scatter_and_zero() {
    int e = blockIdx.x * blockDim.x + threadIdx.x;
    if (e < 2 * H) d_sums[e] = 0.0f;
    if (e < N_EDGES) {
        int r = d_regid[e];
        int pos = atomicAdd(&d_cursor[r], 1);
        d_sorted[pos] = e + 1;
    }
}

// ---------------- 2) Q0/Q1: 8 checkpoint chunks x rank-1 updates -----------
// grid = 256: (blockIdx & 31) = m-group, (blockIdx >> 5) = chunk of 9 ranks
__global__ void __launch_bounds__(128) k_q(const float* w1, const float* b1,
                                           const float* b2, const float* w2) {
    __shared__ float w2sh[128][H + 1];
    __shared__ float tbs[H];
    __shared__ int   rankOf[H], idxOf[H];
    __shared__ float mb[H], mw[H], dB[H], dW[H];
    __shared__ int   cix[H];

    int t = threadIdx.x;
    int mg = blockIdx.x & 31, chunk = blockIdx.x >> 5;
    int r0 = chunk * 9;
    int rend = (r0 + 9 < NREG) ? r0 + 9 : NREG;
    int mbase = mg * 128;

    for (int i2 = t; i2 < 128 * H; i2 += 128) {
        int ml = i2 >> 6, k = i2 & 63;
        w2sh[ml][k] = w2[(mbase + ml) * H + k];
    }
    if (t < H) tbs[t] = bp_of(w1, b1, t);
    __syncthreads();
    if (t < H) {
        float my = tbs[t];
        int rank = 0;
        for (int j = 0; j < H; j++) {
            float tj = tbs[j];
            rank += (tj < my) || (tj == my && j < t);
        }
        rankOf[t] = rank;
        idxOf[rank] = t;
    }
    __syncthreads();
    if (t < H) {
        int k = t;
        float w = w1[k], b = b1[k];
        int rk = rankOf[k];
        bool act = (w > 0.0f) ? (rk < r0) : ((w < 0.0f) ? (rk >= r0) : (b > 0.0f));
        mb[k] = act ? b : 0.0f;
        mw[k] = act ? w : 0.0f;
        int kr = idxOf[t];
        float wr = w1[kr], br = b1[kr];
        float sgn = (wr > 0.0f) ? 1.0f : -1.0f;
        dB[t] = sgn * br;
        dW[t] = sgn * wr;
        cix[t] = kr;
    }
    __syncthreads();

    int m = mbase + t;
    int i = m >> 6, o = m & 63;
    int p = (i >> 1) * 128 + 2 * o + (i & 1);   // pair-permuted index
    const float* row = w2sh[t];
    float q0 = b2[m];
    float q1 = 0.0f;
    #pragma unroll 8
    for (int k = 0; k < H; k++) {
        float v = row[k];
        q0 = fmaf(mb[k], v, q0);
        q1 = fmaf(mw[k], v, q1);
    }
    for (int r = r0; r < rend; r++) {
        d_Qbuf[r * (2 * HH) + p]      = q0;
        d_Qbuf[r * (2 * HH) + HH + p] = q1;
        if (r < H) {
            float v = row[cix[r]];
            q0 = fmaf(dB[r], v, q0);
            q1 = fmaf(dW[r], v, q1);
        }
    }
}

// ---------------- 3) message + scatter-add (hot; warp-autonomous) ----------
__global__ void __launch_bounds__(128, 6) k_msg(const float* x, const float* ea,
                                                const int* ei) {
    __shared__ float2 xs[WARPS][GE][32];    // {x[2c], x[2c+1]} per edge
    __shared__ float  sa[WARPS][GE];
    __shared__ int    ssrc[WARPS][GE];
    __shared__ int    sdst[WARPS][GE];
    __shared__ int    sreg[WARPS][GE];

    int w = threadIdx.x >> 5;
    int lane = threadIdx.x & 31;
    int sbase = blockIdx.x * BLK_SLOTS + w * GE;

    if (lane < GE) {
        int slot = sbase + lane;
        int eid1 = (slot < EPAD) ? d_sorted[slot] : 0;
        int src = -1, dst = 0, r = -1;
        float a = 0.0f;
        if (eid1 > 0) {
            int eid = eid1 - 1;
            a = ea[eid];
            src = ei[eid];
            dst = ei[N_EDGES + eid];
            r = d_regid[eid];
            if (src < 0 || src >= N_NODES || dst < 0 || dst >= N_NODES) {
                src = -1; dst = 0;
            }
        }
        sa[w][lane] = a; ssrc[w][lane] = src;
        sdst[w][lane] = dst; sreg[w][lane] = r;
    }
    __syncwarp();
    int rr = -1;
    #pragma unroll
    for (int j = 0; j < GE; j++) { int rg = sreg[w][j]; rr = (rg > rr) ? rg : rr; }
    if (rr < 0) return;

    #pragma unroll
    for (int j = 0; j < GE; j++) {
        int s = ssrc[w][j];
        float2 v = make_float2(0.0f, 0.0f);
        if (s >= 0) v = *reinterpret_cast<const float2*>(x + s * H + 2 * lane);
        xs[w][j][lane] = v;
    }
    __syncwarp();

    const float* Qp = d_Qbuf + rr * (2 * HH);
    float a0a[GE], a1a[GE], a0b[GE], a1b[GE];
    #pragma unroll
    for (int j = 0; j < GE; j++) { a0a[j] = 0.f; a1a[j] = 0.f; a0b[j] = 0.f; a1b[j] = 0.f; }

    #pragma unroll 4
    for (int c = 0; c < 32; c++) {
        const float* base = Qp + c * 128 + 2 * lane;
        float2 q0a = *reinterpret_cast<const float2*>(base);
        float2 q0b = *reinterpret_cast<const float2*>(base + 64);
        float2 q1a = *reinterpret_cast<const float2*>(base + HH);
        float2 q1b = *reinterpret_cast<const float2*>(base + HH + 64);
        #pragma unroll
        for (int j = 0; j < GE; j++) {
            float2 xv = xs[w][j][c];
            a0a[j] = fmaf(xv.x, q0a.x, a0a[j]); a0a[j] = fmaf(xv.y, q0a.y, a0a[j]);
            a0b[j] = fmaf(xv.x, q0b.x, a0b[j]); a0b[j] = fmaf(xv.y, q0b.y, a0b[j]);
            a1a[j] = fmaf(xv.x, q1a.x, a1a[j]); a1a[j] = fmaf(xv.y, q1a.y, a1a[j]);
            a1b[j] = fmaf(xv.x, q1b.x, a1b[j]); a1b[j] = fmaf(xv.y, q1b.y, a1b[j]);
        }
    }
    #pragma unroll
    for (int j = 0; j < GE; j++) {
        bool live = (ssrc[w][j] >= 0);
        float aa = sa[w][j];
        float va = live ? fmaf(aa, a1a[j], a0a[j]) : 0.0f;
        float vb = live ? fmaf(aa, a1b[j], a0b[j]) : 0.0f;
        float vah = __shfl_down_sync(0xFFFFFFFF, va, 1);
        float vbh = __shfl_down_sync(0xFFFFFFFF, vb, 1);
        if (live && (lane & 1) == 0) {
            float* p = d_agg + sdst[w][j] * H + lane;
            asm volatile("red.global.add.v2.f32 [%0], {%1, %2};"
                         :: "l"(p), "f"(va), "f"(vah) : "memory");
            asm volatile("red.global.add.v2.f32 [%0], {%1, %2};"
                         :: "l"(p + 32), "f"(vb), "f"(vbh) : "memory");
        }
    }
}

// ---------------- 4) root GEMM + bias + agg; fewer barriers ----------------
__global__ void __launch_bounds__(256) k_root(const float* x, const float* rw,
                                              const float* cb, float* out) {
    __shared__ float rws[HH];        // transposed root_w: rws[i*64+o]
    __shared__ float xsn[NPB][H];    // all 32 nodes staged once
    __shared__ float red[256];
    int t = threadIdx.x;
    int n0 = blockIdx.x * NPB;
    for (int idx = t; idx < HH; idx += 256) {
        int oo = idx >> 6, ii = idx & 63;
        rws[ii * H + oo] = rw[idx];
    }
    for (int idx = t; idx < NPB * H; idx += 256) {
        int nl = idx >> 6, ii = idx & 63;
        xsn[nl][ii] = x[(n0 + nl) * H + ii];
    }
    __syncthreads();
    int o = t & 63, q = t >> 6;      // q = 0..3, each handles 8 nodes
    float cbo = cb[o];
    float psum = 0.0f, psq = 0.0f;
    #pragma unroll
    for (int c = 0; c < NPB / 4; c++) {
        int nl = q * (NPB / 4) + c;
        float acc = 0.0f;
        #pragma unroll 8
        for (int i = 0; i < H; i++) acc = fmaf(xsn[nl][i], rws[i * H + o], acc);
        float val = acc + d_agg[(n0 + nl) * H + o] + cbo;
        out[(n0 + nl) * H + o] = val;
        psum += val;
        psq = fmaf(val, val, psq);
    }
    red[t] = psum; __syncthreads();
    if (q < 2) red[t] += red[t + 128];
    __syncthreads();
    if (q == 0) atomicAdd(&d_sums[o], red[t] + red[t + 64]);
    __syncthreads();
    red[t] = psq; __syncthreads();
    if (q < 2) red[t] += red[t + 128];
    __syncthreads();
    if (q == 0) atomicAdd(&d_sums[H + o], red[t] + red[t + 64]);
}

// ---------------- 5) BN + relu + residual, then reset scratch for replay ---
__global__ void k_fin(const float* x, const float* gamma,
                      const float* beta, float* out) {
    int idx = blockIdx.x * blockDim.x + threadIdx.x;
    if (idx < N_NODES * H) {
        int o = idx & 63;
        const float invN = 1.0f / (float)N_NODES;
        float mean = d_sums[o] * invN;
        float var  = d_sums[H + o] * invN - mean * mean;
        float istd = rsqrtf(var + 1e-5f);
        float v = out[idx];
        float bn = fmaf((v - mean) * istd, gamma[o], beta[o]);
        out[idx] = x[idx] + fmaxf(bn, 0.0f);
        d_agg[idx] = 0.0f;
        if (idx < EPAD) d_sorted[idx] = 0;
        if (idx < NREG) { d_hist[idx] = 0; d_cursor[idx] = 0; }
    }
}

extern "C" void kernel_launch(void* const* d_in, const int* in_sizes, int n_in,
                              void* d_out, int out_size) {
    const float* x     = (const float*)d_in[0];
    const float* ea    = (const float*)d_in[1];
    const int*   ei    = (const int*)d_in[2];
    const float* w1    = (const float*)d_in[3];
    const float* b1    = (const float*)d_in[4];
    const float* w2    = (const float*)d_in[5];
    const float* b2    = (const float*)d_in[6];
    const float* rw    = (const float*)d_in[7];
    const float* cb    = (const float*)d_in[8];
    const float* gamma = (const float*)d_in[9];
    const float* beta  = (const float*)d_in[10];
    float* out = (float*)d_out;

    k_region<<<(N_EDGES + 255) / 256, 256>>>(ea, w1, b1);
    k_scatter_and_zero<<<(N_EDGES + 255) / 256, 256>>>();
    k_q<<<256, 128>>>(w1, b1, b2, w2);
    k_msg<<<(EPAD + BLK_SLOTS - 1) / BLK_SLOTS, 128>>>(x, ea, ei);  // profiled slot
    k_root<<<RBLOCKS, 256>>>(x, rw, cb, out);
    k_fin<<<(N_NODES * H + 255) / 256, 256>>>(x, gamma, beta, out);
}